// round 11
// baseline (speedup 1.0000x reference)
#include <cuda_runtime.h>
#include <cuda_fp16.h>
#include <cuda_fp8.h>

#define N_ENTITY 500000
#define N_REL    32
#define DIM      64
#define NHOP     2
#define N_ITEM   10000
#define N_MEM    32
#define BATCH    4096
#define HIST     50

#define FP8_SCALE     16.0f
#define FP8_INV_SCALE 0.0625f

#define HALF_E (N_ENTITY / 2)   // 250000

// Static scratch (allocation-free):
__device__ float g_acc[N_ITEM * DIM];   // 2.56 MB: per-item accumulated emb
__device__ float g_ph[N_ENTITY];        // 2 MB: entity_emb . w_h
__device__ float g_pt[N_ENTITY];        // 2 MB: entity_emb . w_t
__device__ float g_pr[N_REL];           // relation projections
__device__ uint4 g_etq[N_ENTITY * 4];   // 32 MB: fp8(e4m3) entity table x16
                                        // (row = 4 x uint4 = 64 fp8)

__device__ __forceinline__ float warp_sum32(float v) {
    #pragma unroll
    for (int off = 16; off > 0; off >>= 1)
        v += __shfl_xor_sync(0xffffffffu, v, off);
    return v;
}

__device__ __forceinline__ float half_sum16(float v) {
    #pragma unroll
    for (int off = 1; off < 16; off <<= 1)
        v += __shfl_xor_sync(0xffffffffu, v, off);
    return v;
}

__device__ __forceinline__ unsigned short f2fp8x2(float a, float b) {
    return (unsigned short)__nv_cvt_float2_to_fp8x2(make_float2(a, b),
                                                    __NV_SATFINITE, __NV_E4M3);
}

__device__ __forceinline__ unsigned int pack8(const float4& a) {
    return (unsigned int)f2fp8x2(a.x * FP8_SCALE, a.y * FP8_SCALE)
         | ((unsigned int)f2fp8x2(a.z * FP8_SCALE, a.w * FP8_SCALE) << 16);
}

// ---------------------------------------------------------------------------
// K0: streaming pass over the entity table: scalar projections + fp8 copy.
// 4 lanes per row, TWO rows per iteration (e, e+HALF_E): all 8 LDG.128
// issued before any FMA -> 2x memory-level parallelism per thread to cover
// DRAM latency at the observed 44% occupancy.
// ---------------------------------------------------------------------------
__global__ __launch_bounds__(256)
void project_kernel(const float* __restrict__ entity_emb,
                    const float* __restrict__ relation_emb,
                    const float* __restrict__ W_w)
{
    const int tid    = blockIdx.x * 256 + threadIdx.x;
    const int quad   = tid >> 2;
    const int q      = tid & 3;               // dim 16-group [16q..16q+16)
    const int n_quad = (gridDim.x * 256) >> 2;

    const float4* W4 = reinterpret_cast<const float4*>(W_w);
    const float4 wh0 = W4[4 * q + 0], wh1 = W4[4 * q + 1];
    const float4 wh2 = W4[4 * q + 2], wh3 = W4[4 * q + 3];
    const float4 wt0 = W4[32 + 4 * q + 0], wt1 = W4[32 + 4 * q + 1];
    const float4 wt2 = W4[32 + 4 * q + 2], wt3 = W4[32 + 4 * q + 3];

    const float4* ee4 = reinterpret_cast<const float4*>(entity_emb);

    for (int e = quad; e < HALF_E; e += n_quad) {
        const int e2 = e + HALF_E;

        // Issue all 8 loads up front (batched MLP).
        const float4* rowA = ee4 + (long long)e  * 16 + 4 * q;
        const float4* rowB = ee4 + (long long)e2 * 16 + 4 * q;
        const float4 a0 = __ldcs(rowA + 0);
        const float4 a1 = __ldcs(rowA + 1);
        const float4 a2 = __ldcs(rowA + 2);
        const float4 a3 = __ldcs(rowA + 3);
        const float4 b0 = __ldcs(rowB + 0);
        const float4 b1 = __ldcs(rowB + 1);
        const float4 b2 = __ldcs(rowB + 2);
        const float4 b3 = __ldcs(rowB + 3);

        uint4 pkA, pkB;
        pkA.x = pack8(a0); pkA.y = pack8(a1); pkA.z = pack8(a2); pkA.w = pack8(a3);
        pkB.x = pack8(b0); pkB.y = pack8(b1); pkB.z = pack8(b2); pkB.w = pack8(b3);
        g_etq[(long long)e  * 4 + q] = pkA;
        g_etq[(long long)e2 * 4 + q] = pkB;

        float shA = a0.x * wh0.x + a0.y * wh0.y + a0.z * wh0.z + a0.w * wh0.w
                  + a1.x * wh1.x + a1.y * wh1.y + a1.z * wh1.z + a1.w * wh1.w
                  + a2.x * wh2.x + a2.y * wh2.y + a2.z * wh2.z + a2.w * wh2.w
                  + a3.x * wh3.x + a3.y * wh3.y + a3.z * wh3.z + a3.w * wh3.w;
        float stA = a0.x * wt0.x + a0.y * wt0.y + a0.z * wt0.z + a0.w * wt0.w
                  + a1.x * wt1.x + a1.y * wt1.y + a1.z * wt1.z + a1.w * wt1.w
                  + a2.x * wt2.x + a2.y * wt2.y + a2.z * wt2.z + a2.w * wt2.w
                  + a3.x * wt3.x + a3.y * wt3.y + a3.z * wt3.z + a3.w * wt3.w;
        float shB = b0.x * wh0.x + b0.y * wh0.y + b0.z * wh0.z + b0.w * wh0.w
                  + b1.x * wh1.x + b1.y * wh1.y + b1.z * wh1.z + b1.w * wh1.w
                  + b2.x * wh2.x + b2.y * wh2.y + b2.z * wh2.z + b2.w * wh2.w
                  + b3.x * wh3.x + b3.y * wh3.y + b3.z * wh3.z + b3.w * wh3.w;
        float stB = b0.x * wt0.x + b0.y * wt0.y + b0.z * wt0.z + b0.w * wt0.w
                  + b1.x * wt1.x + b1.y * wt1.y + b1.z * wt1.z + b1.w * wt1.w
                  + b2.x * wt2.x + b2.y * wt2.y + b2.z * wt2.z + b2.w * wt2.w
                  + b3.x * wt3.x + b3.y * wt3.y + b3.z * wt3.z + b3.w * wt3.w;

        #pragma unroll
        for (int off = 1; off < 4; off <<= 1) {
            shA += __shfl_xor_sync(0xffffffffu, shA, off);
            stA += __shfl_xor_sync(0xffffffffu, stA, off);
            shB += __shfl_xor_sync(0xffffffffu, shB, off);
            stB += __shfl_xor_sync(0xffffffffu, stB, off);
        }
        if (q == 0) {
            g_ph[e]  = shA; g_pt[e]  = stA;
            g_ph[e2] = shB; g_pt[e2] = stB;
        }
    }

    // Relation projections: warp 0 of block 0 (16-lane layout).
    if (blockIdx.x == 0 && threadIdx.x < 32) {
        const int ll = threadIdx.x & 15;
        const float4 wr = W4[16 + ll];
        const int half = threadIdx.x >> 4;
        for (int rr = half; rr < N_REL; rr += 2) {
            const float4 v = reinterpret_cast<const float4*>(relation_emb)[rr * (DIM / 4) + ll];
            float s = v.x * wr.x + v.y * wr.y + v.z * wr.z + v.w * wr.w;
            #pragma unroll
            for (int off = 1; off < 16; off <<= 1)
                s += __shfl_xor_sync(0xffffffffu, s, off);
            if (ll == 0) g_pr[rr] = s;
        }
    }
}

// ---------------------------------------------------------------------------
// K1 (fused): attention weights + weighted tail accumulation.
// ONE WARP PER ITEM, no __syncthreads, no shared atomics.
// Stage 1 (lane = memory): scalar-projection logits, per-hop in-warp softmax.
// Stage 2 (halfwarp = memory, lane ll owns dims [4ll,4ll+4)): fp8 gather loop.
// ---------------------------------------------------------------------------
__global__ __launch_bounds__(256)
void item_attn_acc_kernel(const float* __restrict__ entity_emb,
                          const float* __restrict__ W_b,
                          const int*   __restrict__ item_ids,
                          const int*   __restrict__ heads,
                          const int*   __restrict__ relations,
                          const int*   __restrict__ tails)
{
    const int wib  = threadIdx.x >> 5;                 // warp in block
    const int item = blockIdx.x * 8 + wib;
    const int lane = threadIdx.x & 31;
    const int half = lane >> 4;
    const int ll   = lane & 15;
    if (item >= N_ITEM) return;

    __shared__ int   s_idx[8][2 * N_MEM];
    __shared__ float s_pi [8][2 * N_MEM];

    // --- Stage 1: logits + softmax, lane = memory slot, both hops ---
    {
        const int base0 = (0 * N_ITEM + item) * N_MEM + lane;
        const int base1 = (1 * N_ITEM + item) * N_MEM + lane;
        const int h0 = heads[base0],     h1 = heads[base1];
        const int r0 = relations[base0], r1 = relations[base1];
        const int t0 = tails[base0],     t1 = tails[base1];
        const float bias = W_b[0];

        const float logit0 = g_ph[h0] + g_pr[r0] + g_pt[t0] + bias;
        const float logit1 = g_ph[h1] + g_pr[r1] + g_pt[t1] + bias;
        const float ev0 = expf(1.0f / (1.0f + expf(-logit0)));
        const float ev1 = expf(1.0f / (1.0f + expf(-logit1)));
        const float d0 = warp_sum32(ev0);
        const float d1 = warp_sum32(ev1);

        s_idx[wib][lane]         = t0;
        s_idx[wib][N_MEM + lane] = t1;
        s_pi [wib][lane]         = ev0 / d0 * FP8_INV_SCALE;
        s_pi [wib][N_MEM + lane] = ev1 / d1 * FP8_INV_SCALE;
    }
    __syncwarp();

    // --- Stage 2: fp8 tail gather; pi already normalized + descaled ---
    const unsigned int* etq32 = reinterpret_cast<const unsigned int*>(g_etq);

    float4 a = make_float4(0.0f, 0.0f, 0.0f, 0.0f);

    #pragma unroll 16
    for (int j = 0; j < 32; ++j) {
        const int m  = 2 * j + half;                   // halfwarp's memory
        const int ti = s_idx[wib][m];                  // LDS broadcast
        const float pi = s_pi[wib][m];
        const unsigned int d = etq32[ti * 16 + ll];    // 4 fp8 = dims [4ll..4ll+4)
        const __half2_raw hlo = __nv_cvt_fp8x2_to_halfraw2(
            (__nv_fp8x2_storage_t)(d & 0xffffu), __NV_E4M3);
        const __half2_raw hhi = __nv_cvt_fp8x2_to_halfraw2(
            (__nv_fp8x2_storage_t)(d >> 16), __NV_E4M3);
        const float2 f01 = __half22float2(*reinterpret_cast<const __half2*>(&hlo));
        const float2 f23 = __half22float2(*reinterpret_cast<const __half2*>(&hhi));
        a.x += pi * f01.x;
        a.y += pi * f01.y;
        a.z += pi * f23.x;
        a.w += pi * f23.y;
    }

    a.x += __shfl_xor_sync(0xffffffffu, a.x, 16);
    a.y += __shfl_xor_sync(0xffffffffu, a.y, 16);
    a.z += __shfl_xor_sync(0xffffffffu, a.z, 16);
    a.w += __shfl_xor_sync(0xffffffffu, a.w, 16);

    if (half == 0) {
        const long long base = (long long)item_ids[item] * (DIM / 4);
        const float4 b = reinterpret_cast<const float4*>(entity_emb)[base + ll];
        float4 o;
        o.x = b.x + a.x;
        o.y = b.y + a.y;
        o.z = b.z + a.z;
        o.w = b.w + a.w;
        reinterpret_cast<float4*>(g_acc)[item * (DIM / 4) + ll] = o;
    }
}

// ---------------------------------------------------------------------------
// K2: user pooling + scoring. One warp per batch row, halfwarp float4 layout.
// ---------------------------------------------------------------------------
__global__ __launch_bounds__(256)
void user_score_kernel(const float* __restrict__ entity_emb,
                       const int*   __restrict__ records_idx,
                       const int*   __restrict__ items,
                       float*       __restrict__ out)
{
    const int warp = (blockIdx.x * blockDim.x + threadIdx.x) >> 5;
    const int lane = threadIdx.x & 31;
    const int half = lane >> 4;
    const int ll   = lane & 15;
    if (warp >= BATCH) return;

    const int* rec = records_idx + warp * HIST;
    const float4* acc4 = reinterpret_cast<const float4*>(g_acc);

    float4 u = make_float4(0.0f, 0.0f, 0.0f, 0.0f);
    #pragma unroll
    for (int i = 0; i < HIST / 2; ++i) {
        const int idx = rec[2 * i + half];
        const float4 a = acc4[idx * (DIM / 4) + ll];
        u.x += a.x; u.y += a.y; u.z += a.z; u.w += a.w;
    }
    u.x += __shfl_xor_sync(0xffffffffu, u.x, 16);
    u.y += __shfl_xor_sync(0xffffffffu, u.y, 16);
    u.z += __shfl_xor_sync(0xffffffffu, u.z, 16);
    u.w += __shfl_xor_sync(0xffffffffu, u.w, 16);

    const int it = items[warp];
    const float4 p = reinterpret_cast<const float4*>(entity_emb)[it * (DIM / 4) + ll];
    float dot = u.x * p.x + u.y * p.y + u.z * p.z + u.w * p.w;
    dot = half_sum16(dot);

    if (lane == 0)
        out[warp] = 1.0f / (1.0f + expf(-dot));
}

// ---------------------------------------------------------------------------
// Launch: [K0, K1, K2]
// ---------------------------------------------------------------------------
extern "C" void kernel_launch(void* const* d_in, const int* in_sizes, int n_in,
                              void* d_out, int out_size)
{
    const float* entity_emb   = (const float*)d_in[0];
    const float* relation_emb = (const float*)d_in[1];
    const float* W_w          = (const float*)d_in[2];
    const float* W_b          = (const float*)d_in[3];
    const int*   item_ids     = (const int*)d_in[4];
    const int*   heads        = (const int*)d_in[5];
    const int*   relations    = (const int*)d_in[6];
    const int*   tails        = (const int*)d_in[7];
    const int*   records_idx  = (const int*)d_in[8];
    const int*   items        = (const int*)d_in[9];
    float*       out          = (float*)d_out;

    project_kernel<<<1184, 256>>>(entity_emb, relation_emb, W_w);

    item_attn_acc_kernel<<<(N_ITEM + 7) / 8, 256>>>(entity_emb, W_b, item_ids,
                                                    heads, relations, tails);

    const int warps_per_block = 256 / 32;
    const int blocks = (BATCH + warps_per_block - 1) / warps_per_block;
    user_score_kernel<<<blocks, 256>>>(entity_emb, records_idx, items, out);
}

// round 12
// speedup vs baseline: 1.1150x; 1.1150x over previous
#include <cuda_runtime.h>
#include <cuda_fp16.h>
#include <cuda_fp8.h>

#define N_ENTITY 500000
#define N_REL    32
#define DIM      64
#define NHOP     2
#define N_ITEM   10000
#define N_MEM    32
#define BATCH    4096
#define HIST     50

#define FP8_SCALE     16.0f
#define FP8_INV_SCALE 0.0625f

// Static scratch (allocation-free):
__device__ float g_acc[N_ITEM * DIM];   // 2.56 MB: per-item accumulated emb
__device__ float g_ph[N_ENTITY];        // 2 MB: entity_emb . w_h
__device__ float g_pt[N_ENTITY];        // 2 MB: entity_emb . w_t
__device__ float g_pr[N_REL];           // relation projections
__device__ uint4 g_etq[N_ENTITY * 4];   // 32 MB: fp8(e4m3) entity table x16
                                        // (row = 4 x uint4 = 64 fp8)

__device__ __forceinline__ float warp_sum32(float v) {
    #pragma unroll
    for (int off = 16; off > 0; off >>= 1)
        v += __shfl_xor_sync(0xffffffffu, v, off);
    return v;
}

__device__ __forceinline__ float half_sum16(float v) {
    #pragma unroll
    for (int off = 1; off < 16; off <<= 1)
        v += __shfl_xor_sync(0xffffffffu, v, off);
    return v;
}

__device__ __forceinline__ unsigned short f2fp8x2(float a, float b) {
    return (unsigned short)__nv_cvt_float2_to_fp8x2(make_float2(a, b),
                                                    __NV_SATFINITE, __NV_E4M3);
}

__device__ __forceinline__ unsigned int pack8(const float4& a) {
    return (unsigned int)f2fp8x2(a.x * FP8_SCALE, a.y * FP8_SCALE)
         | ((unsigned int)f2fp8x2(a.z * FP8_SCALE, a.w * FP8_SCALE) << 16);
}

// ---------------------------------------------------------------------------
// K0 (R10 form — measured 28.5us, at the mixed read/write stream ceiling):
// 4 lanes per row; each lane: 4 LDG.128 (.cs evict-first), one STG.128 of
// 16 fp8, 2-step shuffle reduce for the two scalar projections.
// ---------------------------------------------------------------------------
__global__ __launch_bounds__(256)
void project_kernel(const float* __restrict__ entity_emb,
                    const float* __restrict__ relation_emb,
                    const float* __restrict__ W_w)
{
    const int tid    = blockIdx.x * 256 + threadIdx.x;
    const int quad   = tid >> 2;
    const int q      = tid & 3;               // dim 16-group [16q..16q+16)
    const int n_quad = (gridDim.x * 256) >> 2;

    const float4* W4 = reinterpret_cast<const float4*>(W_w);
    const float4 wh0 = W4[4 * q + 0], wh1 = W4[4 * q + 1];
    const float4 wh2 = W4[4 * q + 2], wh3 = W4[4 * q + 3];
    const float4 wt0 = W4[32 + 4 * q + 0], wt1 = W4[32 + 4 * q + 1];
    const float4 wt2 = W4[32 + 4 * q + 2], wt3 = W4[32 + 4 * q + 3];

    for (int e = quad; e < N_ENTITY; e += n_quad) {
        const float4* row = reinterpret_cast<const float4*>(entity_emb) + e * 16 + 4 * q;
        const float4 v0 = __ldcs(row + 0);
        const float4 v1 = __ldcs(row + 1);
        const float4 v2 = __ldcs(row + 2);
        const float4 v3 = __ldcs(row + 3);

        uint4 pk;
        pk.x = pack8(v0);
        pk.y = pack8(v1);
        pk.z = pack8(v2);
        pk.w = pack8(v3);
        g_etq[e * 4 + q] = pk;

        float sh = v0.x * wh0.x + v0.y * wh0.y + v0.z * wh0.z + v0.w * wh0.w
                 + v1.x * wh1.x + v1.y * wh1.y + v1.z * wh1.z + v1.w * wh1.w
                 + v2.x * wh2.x + v2.y * wh2.y + v2.z * wh2.z + v2.w * wh2.w
                 + v3.x * wh3.x + v3.y * wh3.y + v3.z * wh3.z + v3.w * wh3.w;
        float st = v0.x * wt0.x + v0.y * wt0.y + v0.z * wt0.z + v0.w * wt0.w
                 + v1.x * wt1.x + v1.y * wt1.y + v1.z * wt1.z + v1.w * wt1.w
                 + v2.x * wt2.x + v2.y * wt2.y + v2.z * wt2.z + v2.w * wt2.w
                 + v3.x * wt3.x + v3.y * wt3.y + v3.z * wt3.z + v3.w * wt3.w;
        #pragma unroll
        for (int off = 1; off < 4; off <<= 1) {
            sh += __shfl_xor_sync(0xffffffffu, sh, off);
            st += __shfl_xor_sync(0xffffffffu, st, off);
        }
        if (q == 0) { g_ph[e] = sh; g_pt[e] = st; }
    }

    // Relation projections: warp 0 of block 0 (16-lane layout).
    if (blockIdx.x == 0 && threadIdx.x < 32) {
        const int ll = threadIdx.x & 15;
        const float4 wr = W4[16 + ll];
        const int half = threadIdx.x >> 4;
        for (int rr = half; rr < N_REL; rr += 2) {
            const float4 v = reinterpret_cast<const float4*>(relation_emb)[rr * (DIM / 4) + ll];
            float s = v.x * wr.x + v.y * wr.y + v.z * wr.z + v.w * wr.w;
            #pragma unroll
            for (int off = 1; off < 16; off <<= 1)
                s += __shfl_xor_sync(0xffffffffu, s, off);
            if (ll == 0) g_pr[rr] = s;
        }
    }
}

// ---------------------------------------------------------------------------
// K1 (R10 form): fused attention weights + weighted tail accumulation.
// ONE WARP PER ITEM, no __syncthreads, no shared atomics.
// ---------------------------------------------------------------------------
__global__ __launch_bounds__(256)
void item_attn_acc_kernel(const float* __restrict__ entity_emb,
                          const float* __restrict__ W_b,
                          const int*   __restrict__ item_ids,
                          const int*   __restrict__ heads,
                          const int*   __restrict__ relations,
                          const int*   __restrict__ tails)
{
    const int wib  = threadIdx.x >> 5;                 // warp in block
    const int item = blockIdx.x * 8 + wib;
    const int lane = threadIdx.x & 31;
    const int half = lane >> 4;
    const int ll   = lane & 15;
    if (item >= N_ITEM) return;

    __shared__ int   s_idx[8][2 * N_MEM];
    __shared__ float s_pi [8][2 * N_MEM];

    // --- Stage 1: logits + softmax, lane = memory slot, both hops ---
    {
        const int base0 = (0 * N_ITEM + item) * N_MEM + lane;
        const int base1 = (1 * N_ITEM + item) * N_MEM + lane;
        const int h0 = heads[base0],     h1 = heads[base1];
        const int r0 = relations[base0], r1 = relations[base1];
        const int t0 = tails[base0],     t1 = tails[base1];
        const float bias = W_b[0];

        const float logit0 = g_ph[h0] + g_pr[r0] + g_pt[t0] + bias;
        const float logit1 = g_ph[h1] + g_pr[r1] + g_pt[t1] + bias;
        const float ev0 = expf(1.0f / (1.0f + expf(-logit0)));
        const float ev1 = expf(1.0f / (1.0f + expf(-logit1)));
        const float d0 = warp_sum32(ev0);
        const float d1 = warp_sum32(ev1);

        s_idx[wib][lane]         = t0;
        s_idx[wib][N_MEM + lane] = t1;
        s_pi [wib][lane]         = ev0 / d0 * FP8_INV_SCALE;
        s_pi [wib][N_MEM + lane] = ev1 / d1 * FP8_INV_SCALE;
    }
    __syncwarp();

    // --- Stage 2: fp8 tail gather; pi already normalized + descaled ---
    const unsigned int* etq32 = reinterpret_cast<const unsigned int*>(g_etq);

    float4 a = make_float4(0.0f, 0.0f, 0.0f, 0.0f);

    #pragma unroll 16
    for (int j = 0; j < 32; ++j) {
        const int m  = 2 * j + half;                   // halfwarp's memory
        const int ti = s_idx[wib][m];                  // LDS broadcast
        const float pi = s_pi[wib][m];
        const unsigned int d = etq32[ti * 16 + ll];    // 4 fp8 = dims [4ll..4ll+4)
        const __half2_raw hlo = __nv_cvt_fp8x2_to_halfraw2(
            (__nv_fp8x2_storage_t)(d & 0xffffu), __NV_E4M3);
        const __half2_raw hhi = __nv_cvt_fp8x2_to_halfraw2(
            (__nv_fp8x2_storage_t)(d >> 16), __NV_E4M3);
        const float2 f01 = __half22float2(*reinterpret_cast<const __half2*>(&hlo));
        const float2 f23 = __half22float2(*reinterpret_cast<const __half2*>(&hhi));
        a.x += pi * f01.x;
        a.y += pi * f01.y;
        a.z += pi * f23.x;
        a.w += pi * f23.y;
    }

    a.x += __shfl_xor_sync(0xffffffffu, a.x, 16);
    a.y += __shfl_xor_sync(0xffffffffu, a.y, 16);
    a.z += __shfl_xor_sync(0xffffffffu, a.z, 16);
    a.w += __shfl_xor_sync(0xffffffffu, a.w, 16);

    if (half == 0) {
        const long long base = (long long)item_ids[item] * (DIM / 4);
        const float4 b = reinterpret_cast<const float4*>(entity_emb)[base + ll];
        float4 o;
        o.x = b.x + a.x;
        o.y = b.y + a.y;
        o.z = b.z + a.z;
        o.w = b.w + a.w;
        reinterpret_cast<float4*>(g_acc)[item * (DIM / 4) + ll] = o;
    }
}

// ---------------------------------------------------------------------------
// K2: user pooling + scoring. One warp per batch row; MLP-batched gathers:
// each unrolled chunk issues 8 independent row loads (4 per halfwarp) from
// the L2-resident g_acc before any accumulation. 6 chunks of 8 + tail of 2.
// ---------------------------------------------------------------------------
__global__ __launch_bounds__(256)
void user_score_kernel(const float* __restrict__ entity_emb,
                       const int*   __restrict__ records_idx,
                       const int*   __restrict__ items,
                       float*       __restrict__ out)
{
    const int warp = (blockIdx.x * blockDim.x + threadIdx.x) >> 5;
    const int lane = threadIdx.x & 31;
    const int half = lane >> 4;
    const int ll   = lane & 15;
    if (warp >= BATCH) return;

    const int* rec = records_idx + warp * HIST;
    const float4* acc4 = reinterpret_cast<const float4*>(g_acc);

    float4 u = make_float4(0.0f, 0.0f, 0.0f, 0.0f);

    #pragma unroll
    for (int c = 0; c < 6; ++c) {
        // Halfwarp handles entries {8c+half, 8c+2+half, 8c+4+half, 8c+6+half}.
        const int i0 = rec[8 * c + 0 + half];
        const int i1 = rec[8 * c + 2 + half];
        const int i2 = rec[8 * c + 4 + half];
        const int i3 = rec[8 * c + 6 + half];
        const float4 a0 = acc4[i0 * (DIM / 4) + ll];
        const float4 a1 = acc4[i1 * (DIM / 4) + ll];
        const float4 a2 = acc4[i2 * (DIM / 4) + ll];
        const float4 a3 = acc4[i3 * (DIM / 4) + ll];
        u.x += a0.x + a1.x + a2.x + a3.x;
        u.y += a0.y + a1.y + a2.y + a3.y;
        u.z += a0.z + a1.z + a2.z + a3.z;
        u.w += a0.w + a1.w + a2.w + a3.w;
    }
    {   // tail: entries 48, 49
        const int i0 = rec[48 + half];
        const float4 a0 = acc4[i0 * (DIM / 4) + ll];
        u.x += a0.x; u.y += a0.y; u.z += a0.z; u.w += a0.w;
    }

    // Merge the two halfwarp partials (same dims, disjoint history subsets).
    u.x += __shfl_xor_sync(0xffffffffu, u.x, 16);
    u.y += __shfl_xor_sync(0xffffffffu, u.y, 16);
    u.z += __shfl_xor_sync(0xffffffffu, u.z, 16);
    u.w += __shfl_xor_sync(0xffffffffu, u.w, 16);

    const int it = items[warp];
    const float4 p = reinterpret_cast<const float4*>(entity_emb)[it * (DIM / 4) + ll];
    float dot = u.x * p.x + u.y * p.y + u.z * p.z + u.w * p.w;
    dot = half_sum16(dot);

    if (lane == 0)
        out[warp] = 1.0f / (1.0f + expf(-dot));
}

// ---------------------------------------------------------------------------
// Launch: [K0, K1, K2]
// ---------------------------------------------------------------------------
extern "C" void kernel_launch(void* const* d_in, const int* in_sizes, int n_in,
                              void* d_out, int out_size)
{
    const float* entity_emb   = (const float*)d_in[0];
    const float* relation_emb = (const float*)d_in[1];
    const float* W_w          = (const float*)d_in[2];
    const float* W_b          = (const float*)d_in[3];
    const int*   item_ids     = (const int*)d_in[4];
    const int*   heads        = (const int*)d_in[5];
    const int*   relations    = (const int*)d_in[6];
    const int*   tails        = (const int*)d_in[7];
    const int*   records_idx  = (const int*)d_in[8];
    const int*   items        = (const int*)d_in[9];
    float*       out          = (float*)d_out;

    project_kernel<<<1184, 256>>>(entity_emb, relation_emb, W_w);

    item_attn_acc_kernel<<<(N_ITEM + 7) / 8, 256>>>(entity_emb, W_b, item_ids,
                                                    heads, relations, tails);

    const int warps_per_block = 256 / 32;
    const int blocks = (BATCH + warps_per_block - 1) / warps_per_block;
    user_score_kernel<<<blocks, 256>>>(entity_emb, records_idx, items, out);
}

// round 13
// speedup vs baseline: 1.1486x; 1.0302x over previous
#include <cuda_runtime.h>
#include <cuda_fp16.h>
#include <cuda_fp8.h>

#define N_ENTITY 500000
#define N_REL    32
#define DIM      64
#define NHOP     2
#define N_ITEM   10000
#define N_MEM    32
#define BATCH    4096
#define HIST     50

#define FP8_SCALE     16.0f
#define FP8_INV_SCALE 0.0625f

// Static scratch (allocation-free):
__device__ float g_acc[N_ITEM * DIM];   // 2.56 MB: per-item accumulated emb
__device__ float g_ph[N_ENTITY];        // 2 MB: entity_emb . w_h
__device__ float g_pt[N_ENTITY];        // 2 MB: entity_emb . w_t
__device__ float g_pr[N_REL];           // relation projections
__device__ uint4 g_etq[N_ENTITY * 4];   // 32 MB: fp8(e4m3) entity table x16
                                        // (row = 4 x uint4 = 64 fp8)

__device__ __forceinline__ float warp_sum32(float v) {
    #pragma unroll
    for (int off = 16; off > 0; off >>= 1)
        v += __shfl_xor_sync(0xffffffffu, v, off);
    return v;
}

__device__ __forceinline__ float half_sum16(float v) {
    #pragma unroll
    for (int off = 1; off < 16; off <<= 1)
        v += __shfl_xor_sync(0xffffffffu, v, off);
    return v;
}

__device__ __forceinline__ unsigned short f2fp8x2(float a, float b) {
    return (unsigned short)__nv_cvt_float2_to_fp8x2(make_float2(a, b),
                                                    __NV_SATFINITE, __NV_E4M3);
}

__device__ __forceinline__ unsigned int pack8(const float4& a) {
    return (unsigned int)f2fp8x2(a.x * FP8_SCALE, a.y * FP8_SCALE)
         | ((unsigned int)f2fp8x2(a.z * FP8_SCALE, a.w * FP8_SCALE) << 16);
}

// ---------------------------------------------------------------------------
// K0 (FROZEN, R10 form — 28.5us, at the mixed read/write stream ceiling):
// 4 lanes per row; each lane: 4 LDG.128 (.cs evict-first), one STG.128 of
// 16 fp8, 2-step shuffle reduce for the two scalar projections.
// ---------------------------------------------------------------------------
__global__ __launch_bounds__(256)
void project_kernel(const float* __restrict__ entity_emb,
                    const float* __restrict__ relation_emb,
                    const float* __restrict__ W_w)
{
    const int tid    = blockIdx.x * 256 + threadIdx.x;
    const int quad   = tid >> 2;
    const int q      = tid & 3;               // dim 16-group [16q..16q+16)
    const int n_quad = (gridDim.x * 256) >> 2;

    const float4* W4 = reinterpret_cast<const float4*>(W_w);
    const float4 wh0 = W4[4 * q + 0], wh1 = W4[4 * q + 1];
    const float4 wh2 = W4[4 * q + 2], wh3 = W4[4 * q + 3];
    const float4 wt0 = W4[32 + 4 * q + 0], wt1 = W4[32 + 4 * q + 1];
    const float4 wt2 = W4[32 + 4 * q + 2], wt3 = W4[32 + 4 * q + 3];

    for (int e = quad; e < N_ENTITY; e += n_quad) {
        const float4* row = reinterpret_cast<const float4*>(entity_emb) + e * 16 + 4 * q;
        const float4 v0 = __ldcs(row + 0);
        const float4 v1 = __ldcs(row + 1);
        const float4 v2 = __ldcs(row + 2);
        const float4 v3 = __ldcs(row + 3);

        uint4 pk;
        pk.x = pack8(v0);
        pk.y = pack8(v1);
        pk.z = pack8(v2);
        pk.w = pack8(v3);
        g_etq[e * 4 + q] = pk;

        float sh = v0.x * wh0.x + v0.y * wh0.y + v0.z * wh0.z + v0.w * wh0.w
                 + v1.x * wh1.x + v1.y * wh1.y + v1.z * wh1.z + v1.w * wh1.w
                 + v2.x * wh2.x + v2.y * wh2.y + v2.z * wh2.z + v2.w * wh2.w
                 + v3.x * wh3.x + v3.y * wh3.y + v3.z * wh3.z + v3.w * wh3.w;
        float st = v0.x * wt0.x + v0.y * wt0.y + v0.z * wt0.z + v0.w * wt0.w
                 + v1.x * wt1.x + v1.y * wt1.y + v1.z * wt1.z + v1.w * wt1.w
                 + v2.x * wt2.x + v2.y * wt2.y + v2.z * wt2.z + v2.w * wt2.w
                 + v3.x * wt3.x + v3.y * wt3.y + v3.z * wt3.z + v3.w * wt3.w;
        #pragma unroll
        for (int off = 1; off < 4; off <<= 1) {
            sh += __shfl_xor_sync(0xffffffffu, sh, off);
            st += __shfl_xor_sync(0xffffffffu, st, off);
        }
        if (q == 0) { g_ph[e] = sh; g_pt[e] = st; }
    }

    // Relation projections: warp 0 of block 0 (16-lane layout).
    if (blockIdx.x == 0 && threadIdx.x < 32) {
        const int ll = threadIdx.x & 15;
        const float4 wr = W4[16 + ll];
        const int half = threadIdx.x >> 4;
        for (int rr = half; rr < N_REL; rr += 2) {
            const float4 v = reinterpret_cast<const float4*>(relation_emb)[rr * (DIM / 4) + ll];
            float s = v.x * wr.x + v.y * wr.y + v.z * wr.z + v.w * wr.w;
            #pragma unroll
            for (int off = 1; off < 16; off <<= 1)
                s += __shfl_xor_sync(0xffffffffu, s, off);
            if (ll == 0) g_pr[rr] = s;
        }
    }
}

// ---------------------------------------------------------------------------
// K1 (FROZEN, R10 form): fused attention weights + weighted tail accumulation.
// ONE WARP PER ITEM, no __syncthreads, no shared atomics.
// ---------------------------------------------------------------------------
__global__ __launch_bounds__(256)
void item_attn_acc_kernel(const float* __restrict__ entity_emb,
                          const float* __restrict__ W_b,
                          const int*   __restrict__ item_ids,
                          const int*   __restrict__ heads,
                          const int*   __restrict__ relations,
                          const int*   __restrict__ tails)
{
    const int wib  = threadIdx.x >> 5;                 // warp in block
    const int item = blockIdx.x * 8 + wib;
    const int lane = threadIdx.x & 31;
    const int half = lane >> 4;
    const int ll   = lane & 15;
    if (item >= N_ITEM) return;

    __shared__ int   s_idx[8][2 * N_MEM];
    __shared__ float s_pi [8][2 * N_MEM];

    // --- Stage 1: logits + softmax, lane = memory slot, both hops ---
    {
        const int base0 = (0 * N_ITEM + item) * N_MEM + lane;
        const int base1 = (1 * N_ITEM + item) * N_MEM + lane;
        const int h0 = heads[base0],     h1 = heads[base1];
        const int r0 = relations[base0], r1 = relations[base1];
        const int t0 = tails[base0],     t1 = tails[base1];
        const float bias = W_b[0];

        const float logit0 = g_ph[h0] + g_pr[r0] + g_pt[t0] + bias;
        const float logit1 = g_ph[h1] + g_pr[r1] + g_pt[t1] + bias;
        const float ev0 = expf(1.0f / (1.0f + expf(-logit0)));
        const float ev1 = expf(1.0f / (1.0f + expf(-logit1)));
        const float d0 = warp_sum32(ev0);
        const float d1 = warp_sum32(ev1);

        s_idx[wib][lane]         = t0;
        s_idx[wib][N_MEM + lane] = t1;
        s_pi [wib][lane]         = ev0 / d0 * FP8_INV_SCALE;
        s_pi [wib][N_MEM + lane] = ev1 / d1 * FP8_INV_SCALE;
    }
    __syncwarp();

    // --- Stage 2: fp8 tail gather; pi already normalized + descaled ---
    const unsigned int* etq32 = reinterpret_cast<const unsigned int*>(g_etq);

    float4 a = make_float4(0.0f, 0.0f, 0.0f, 0.0f);

    #pragma unroll 16
    for (int j = 0; j < 32; ++j) {
        const int m  = 2 * j + half;                   // halfwarp's memory
        const int ti = s_idx[wib][m];                  // LDS broadcast
        const float pi = s_pi[wib][m];
        const unsigned int d = etq32[ti * 16 + ll];    // 4 fp8 = dims [4ll..4ll+4)
        const __half2_raw hlo = __nv_cvt_fp8x2_to_halfraw2(
            (__nv_fp8x2_storage_t)(d & 0xffffu), __NV_E4M3);
        const __half2_raw hhi = __nv_cvt_fp8x2_to_halfraw2(
            (__nv_fp8x2_storage_t)(d >> 16), __NV_E4M3);
        const float2 f01 = __half22float2(*reinterpret_cast<const __half2*>(&hlo));
        const float2 f23 = __half22float2(*reinterpret_cast<const __half2*>(&hhi));
        a.x += pi * f01.x;
        a.y += pi * f01.y;
        a.z += pi * f23.x;
        a.w += pi * f23.y;
    }

    a.x += __shfl_xor_sync(0xffffffffu, a.x, 16);
    a.y += __shfl_xor_sync(0xffffffffu, a.y, 16);
    a.z += __shfl_xor_sync(0xffffffffu, a.z, 16);
    a.w += __shfl_xor_sync(0xffffffffu, a.w, 16);

    if (half == 0) {
        const long long base = (long long)item_ids[item] * (DIM / 4);
        const float4 b = reinterpret_cast<const float4*>(entity_emb)[base + ll];
        float4 o;
        o.x = b.x + a.x;
        o.y = b.y + a.y;
        o.z = b.z + a.z;
        o.w = b.w + a.w;
        reinterpret_cast<float4*>(g_acc)[item * (DIM / 4) + ll] = o;
    }
}

// ---------------------------------------------------------------------------
// K2: user pooling + scoring. One warp per batch row.
// All 50 history indices preloaded into registers by 2 coalesced loads
// (lane l holds rec[l] and rec[32+l]); per-iteration index comes from
// __shfl_sync -> all 25 row gathers per thread are INDEPENDENT (no
// idx-load -> row-load pointer chase). Two accumulators relax FADD chains.
// ---------------------------------------------------------------------------
__global__ __launch_bounds__(256)
void user_score_kernel(const float* __restrict__ entity_emb,
                       const int*   __restrict__ records_idx,
                       const int*   __restrict__ items,
                       float*       __restrict__ out)
{
    const int warp = (blockIdx.x * blockDim.x + threadIdx.x) >> 5;
    const int lane = threadIdx.x & 31;
    const int half = lane >> 4;
    const int ll   = lane & 15;
    if (warp >= BATCH) return;

    const int* rec = records_idx + warp * HIST;

    // Preload the whole history into registers (2 independent coalesced loads).
    const int v1 = rec[lane];                                    // rec[0..31]
    const int v2 = (lane < HIST - 32) ? rec[32 + lane] : 0;      // rec[32..49]

    const float4* acc4 = reinterpret_cast<const float4*>(g_acc);

    float4 u0 = make_float4(0.0f, 0.0f, 0.0f, 0.0f);
    float4 u1 = make_float4(0.0f, 0.0f, 0.0f, 0.0f);

    // Halfwarp h handles entries {2j + h}. For j < 16 the entry index is
    // < 32 (register v1); for j >= 16 it is 32..49 (register v2).
    #pragma unroll
    for (int j = 0; j < HIST / 2; ++j) {
        const int m  = 2 * j + half;
        const int ti = (j < 16) ? __shfl_sync(0xffffffffu, v1, m)
                                : __shfl_sync(0xffffffffu, v2, m - 32);
        const float4 a = acc4[ti * (DIM / 4) + ll];
        if (j & 1) {
            u1.x += a.x; u1.y += a.y; u1.z += a.z; u1.w += a.w;
        } else {
            u0.x += a.x; u0.y += a.y; u0.z += a.z; u0.w += a.w;
        }
    }

    float4 u;
    u.x = u0.x + u1.x;
    u.y = u0.y + u1.y;
    u.z = u0.z + u1.z;
    u.w = u0.w + u1.w;

    // Merge the two halfwarp partials (same dims, disjoint history subsets).
    u.x += __shfl_xor_sync(0xffffffffu, u.x, 16);
    u.y += __shfl_xor_sync(0xffffffffu, u.y, 16);
    u.z += __shfl_xor_sync(0xffffffffu, u.z, 16);
    u.w += __shfl_xor_sync(0xffffffffu, u.w, 16);

    const int it = items[warp];
    const float4 p = reinterpret_cast<const float4*>(entity_emb)[it * (DIM / 4) + ll];
    float dot = u.x * p.x + u.y * p.y + u.z * p.z + u.w * p.w;
    dot = half_sum16(dot);

    if (lane == 0)
        out[warp] = 1.0f / (1.0f + expf(-dot));
}

// ---------------------------------------------------------------------------
// Launch: [K0, K1, K2]
// ---------------------------------------------------------------------------
extern "C" void kernel_launch(void* const* d_in, const int* in_sizes, int n_in,
                              void* d_out, int out_size)
{
    const float* entity_emb   = (const float*)d_in[0];
    const float* relation_emb = (const float*)d_in[1];
    const float* W_w          = (const float*)d_in[2];
    const float* W_b          = (const float*)d_in[3];
    const int*   item_ids     = (const int*)d_in[4];
    const int*   heads        = (const int*)d_in[5];
    const int*   relations    = (const int*)d_in[6];
    const int*   tails        = (const int*)d_in[7];
    const int*   records_idx  = (const int*)d_in[8];
    const int*   items        = (const int*)d_in[9];
    float*       out          = (float*)d_out;

    project_kernel<<<1184, 256>>>(entity_emb, relation_emb, W_w);

    item_attn_acc_kernel<<<(N_ITEM + 7) / 8, 256>>>(entity_emb, W_b, item_ids,
                                                    heads, relations, tails);

    const int warps_per_block = 256 / 32;
    const int blocks = (BATCH + warps_per_block - 1) / warps_per_block;
    user_score_kernel<<<blocks, 256>>>(entity_emb, records_idx, items, out);
}